// round 15
// baseline (speedup 1.0000x reference)
#include <cuda_runtime.h>

#define BATCH 32
#define DIM   1024
#define INNER 2048

// ---------------- device scratch ----------------
__device__ __align__(16) float g_qkvpart[8 * BATCH * 4096];    // [dc][b][j]
__device__ __align__(16) float g_colpart[16 * BATCH * INNER];  // [z][b][j]
__device__ __align__(16) float g_kp[BATCH * INNER];
__device__ __align__(16) float g_qp[BATCH * INNER];
__device__ __align__(16) float g_dv[BATCH * INNER];
__device__ __align__(16) float g_outv[BATCH * INNER];
__device__ __align__(16) float g_opart[64 * BATCH * DIM];      // [ic][b][jo]

// ---------------- K1: fused colsum(W) + qkv partial GEMM -------------
__global__ __launch_bounds__(256) void k_pass1(const float* __restrict__ x,
                                               const float* __restrict__ Wq,
                                               const float* __restrict__ Wk,
                                               const float* __restrict__ Wv,
                                               const float* __restrict__ W) {
    __shared__ __align__(16) float shx[32 * 128];
    const int bid = blockIdx.x, tid = threadIdx.x;

    if (bid < 1024) {
        // ---- colsum branch: block = (jc, b, z); 128 rows x 1024 cols ----
        const int jc = bid & 1, b = (bid >> 1) & 31, z = bid >> 6;
        const int c = jc * 1024 + tid * 4;
        const float4* p = (const float4*)(W + ((size_t)(b * INNER + z * 128)) * INNER + c);
        float4 a0 = {0,0,0,0}, a1 = {0,0,0,0}, a2 = {0,0,0,0}, a3 = {0,0,0,0};
        for (int r = 0; r < 128; r += 4) {
            float4 v0 = __ldcs(&p[(size_t)(r + 0) * 512]);
            float4 v1 = __ldcs(&p[(size_t)(r + 1) * 512]);
            float4 v2 = __ldcs(&p[(size_t)(r + 2) * 512]);
            float4 v3 = __ldcs(&p[(size_t)(r + 3) * 512]);
            a0.x += v0.x; a0.y += v0.y; a0.z += v0.z; a0.w += v0.w;
            a1.x += v1.x; a1.y += v1.y; a1.z += v1.z; a1.w += v1.w;
            a2.x += v2.x; a2.y += v2.y; a2.z += v2.z; a2.w += v2.w;
            a3.x += v3.x; a3.y += v3.y; a3.z += v3.z; a3.w += v3.w;
        }
        float4 s;
        s.x = (a0.x + a1.x) + (a2.x + a3.x);
        s.y = (a0.y + a1.y) + (a2.y + a3.y);
        s.z = (a0.z + a1.z) + (a2.z + a3.z);
        s.w = (a0.w + a1.w) + (a2.w + a3.w);
        *(float4*)(g_colpart + ((size_t)(z * 32 + b)) * INNER + c) = s;
    } else {
        // ---- qkv partial GEMM branch ----
        const int qid = bid - 1024;
        const int jc = qid & 15, dc = qid >> 4;
        for (int t = tid; t < 32 * 128; t += 256) {
            int b = t >> 7, dd = t & 127;
            shx[t] = x[b * DIM + dc * 128 + dd];
        }
        __syncthreads();

        const int j = jc * 256 + tid;  // 0..4095
        const float* Wm; int col, ncols;
        if (j < 1024)      { Wm = Wq; col = j;        ncols = 1024; }
        else if (j < 2048) { Wm = Wk; col = j - 1024; ncols = 1024; }
        else               { Wm = Wv; col = j - 2048; ncols = 2048; }

        float acc[32];
#pragma unroll
        for (int b = 0; b < 32; b++) acc[b] = 0.f;
        const float* wp = Wm + (size_t)(dc * 128) * ncols + col;
        for (int dd = 0; dd < 128; dd += 4) {
            float w0 = wp[(size_t)(dd + 0) * ncols];
            float w1 = wp[(size_t)(dd + 1) * ncols];
            float w2 = wp[(size_t)(dd + 2) * ncols];
            float w3 = wp[(size_t)(dd + 3) * ncols];
#pragma unroll
            for (int b = 0; b < 32; b++) {
                const float4 xv = *(const float4*)&shx[b * 128 + dd];
                acc[b] = fmaf(xv.x, w0, fmaf(xv.y, w1, fmaf(xv.z, w2, fmaf(xv.w, w3, acc[b]))));
            }
        }
#pragma unroll
        for (int b = 0; b < 32; b++)
            g_qkvpart[(size_t)(dc * 32 + b) * 4096 + j] = acc[b];
    }
}

// ---------------- K2: beta, kp, qp, dv (from L2-hot partials) --------
__device__ __forceinline__ float sum8_qkv(int b, int j) {
    float s = 0.f;
#pragma unroll
    for (int dc = 0; dc < 8; dc++) s += g_qkvpart[(size_t)(dc * 32 + b) * 4096 + j];
    return s;
}

__device__ __forceinline__ float feat(int b, int j, int base, const float* __restrict__ bias) {
    const int c = j & 1023;
    float v = sum8_qkv(b, base + c) + bias[c];
    v = (j < 1024) ? v : -v;
    return fmaxf(v, 0.f);
}

__global__ __launch_bounds__(256) void k_mid(const float* __restrict__ x,
                                             const float* __restrict__ Wb,
                                             const float* __restrict__ bb,
                                             const float* __restrict__ bq,
                                             const float* __restrict__ bk,
                                             const float* __restrict__ bv) {
    const int b = blockIdx.y, jc = blockIdx.x, tid = threadIdx.x;

    float s = 0.f;
    for (int d = tid; d < DIM; d += 256) s += x[b * DIM + d] * Wb[d];
#pragma unroll
    for (int o = 16; o; o >>= 1) s += __shfl_down_sync(0xffffffffu, s, o);
    __shared__ float shr[8];
    __shared__ float sbeta;
    if ((tid & 31) == 0) shr[tid >> 5] = s;
    __syncthreads();
    if (tid == 0) {
        float t = 0.f;
#pragma unroll
        for (int u = 0; u < 8; u++) t += shr[u];
        t += bb[0];
        sbeta = 1.f / (1.f + expf(-t));
    }
    __syncthreads();
    const float beta = sbeta;

    const int j = jc * 256 + tid;
    const int jm = (j + INNER - 1) & (INNER - 1);

    const float kpv = feat(b, j, 1024, bk) * feat(b, jm, 1024, bk);
    g_kp[b * INNER + j] = kpv;
    g_qp[b * INNER + j] = feat(b, j, 0, bq) * feat(b, jm, 0, bq);

    const float vv = sum8_qkv(b, 2048 + j) + bv[j];
    float cs = 0.f;
#pragma unroll
    for (int z = 0; z < 16; z++) cs += g_colpart[(size_t)(z * 32 + b) * INNER + j];
    g_dv[b * INNER + j] = beta * (vv - cs * kpv);
}

// ---------------- K3: W_new = W + dv⊗kp, fused row-sum --------------
// grid (256 rowgroups of 8, 32 b), 256 threads = 8 warps, one warp per row.
__global__ __launch_bounds__(256) void k_update(const float* __restrict__ W,
                                                float* __restrict__ wnew) {
    const int b = blockIdx.y, tid = threadIdx.x;
    const int i0 = blockIdx.x * 8;
    __shared__ __align__(16) float4 shkp[512];
    const float4* kpv4 = (const float4*)(g_kp + b * INNER);
    for (int t = tid; t < 512; t += 256) shkp[t] = kpv4[t];
    __syncthreads();

    const int w = tid >> 5, lane = tid & 31;
    const int i = i0 + w;
    const size_t base = ((size_t)b * INNER + i) * INNER;
    const float4* Wr = (const float4*)(W + base);
    float4* Or = (float4*)(wnew + base);
    const float dvi = g_dv[b * INNER + i];

    float lsum = 0.f;
#pragma unroll
    for (int t = lane; t < 512; t += 32) {
        float4 wv = __ldcs(&Wr[t]);
        float4 kp4 = shkp[t];
        float4 r;
        r.x = fmaf(dvi, kp4.x, wv.x);
        r.y = fmaf(dvi, kp4.y, wv.y);
        r.z = fmaf(dvi, kp4.z, wv.z);
        r.w = fmaf(dvi, kp4.w, wv.w);
        __stcs(&Or[t], r);
        lsum += (r.x + r.y) + (r.z + r.w);
    }
#pragma unroll
    for (int o = 16; o; o >>= 1) lsum += __shfl_down_sync(0xffffffffu, lsum, o);
    if (lane == 0) g_outv[b * INNER + i] = lsum * g_qp[b * INNER + i];
}

// ---------------- K4: out partials = outv @ Wo -----------------------
// grid (64 ic, 4 bg), 256 threads: each thread owns 4 consecutive jo via
// float4 loads of Wo; acc = 8 batches x float4. FMA-bound by design.
__global__ __launch_bounds__(256) void k_outpart(const float* __restrict__ Wo) {
    __shared__ __align__(16) float sh[8 * 32];
    const int ic = blockIdx.x, bg = blockIdx.y, tid = threadIdx.x;
    if (tid < 8 * 32) {
        int bb = tid >> 5, ii = tid & 31;
        sh[tid] = g_outv[(bg * 8 + bb) * INNER + ic * 32 + ii];
    }
    __syncthreads();

    float4 acc[8];
#pragma unroll
    for (int bb = 0; bb < 8; bb++) acc[bb] = make_float4(0.f, 0.f, 0.f, 0.f);

    const float4* wrow = (const float4*)(Wo + (size_t)(ic * 32) * DIM) + tid;
#pragma unroll 4
    for (int ii = 0; ii < 32; ii++) {
        const float4 w = wrow[(size_t)ii * (DIM / 4)];
#pragma unroll
        for (int bb = 0; bb < 8; bb++) {
            const float ov = sh[bb * 32 + ii];
            acc[bb].x = fmaf(ov, w.x, acc[bb].x);
            acc[bb].y = fmaf(ov, w.y, acc[bb].y);
            acc[bb].z = fmaf(ov, w.z, acc[bb].z);
            acc[bb].w = fmaf(ov, w.w, acc[bb].w);
        }
    }
#pragma unroll
    for (int bb = 0; bb < 8; bb++)
        *((float4*)(g_opart + (size_t)(ic * 32 + bg * 8 + bb) * DIM) + tid) = acc[bb];
}

// ---------------- K5: out finalize -----------------------------------
__global__ __launch_bounds__(256) void k_outfinal(const float* __restrict__ bo,
                                                  float* __restrict__ out) {
    const int idx = blockIdx.x * 256 + threadIdx.x;  // 32768
    const int jo = idx & 1023, b = idx >> 10;
    float s = bo[jo];
#pragma unroll
    for (int ic = 0; ic < 64; ic++) s += g_opart[(size_t)(ic * 32 + b) * DIM + jo];
    out[idx] = s;
}

// ---------------- launch ---------------------------------------------
extern "C" void kernel_launch(void* const* d_in, const int* in_sizes, int n_in,
                              void* d_out, int out_size) {
    const float* x  = (const float*)d_in[0];
    const float* W  = (const float*)d_in[1];
    const float* Wq = (const float*)d_in[2];
    const float* bq = (const float*)d_in[3];
    const float* Wk = (const float*)d_in[4];
    const float* bk = (const float*)d_in[5];
    const float* Wv = (const float*)d_in[6];
    const float* bv = (const float*)d_in[7];
    const float* Wo = (const float*)d_in[8];
    const float* bo = (const float*)d_in[9];
    const float* Wb = (const float*)d_in[10];
    const float* bb = (const float*)d_in[11];

    float* out  = (float*)d_out;
    float* wnew = out + BATCH * DIM;

    k_pass1   <<<1152,          256>>>(x, Wq, Wk, Wv, W);
    k_mid     <<<dim3(8, 32),   256>>>(x, Wb, bb, bq, bk, bv);
    k_update  <<<dim3(256, 32), 256>>>(W, wnew);
    k_outpart <<<dim3(64, 4),   256>>>(Wo);
    k_outfinal<<<128,           256>>>(bo, out);
}

// round 16
// speedup vs baseline: 1.1021x; 1.1021x over previous
#include <cuda_runtime.h>

#define BATCH 32
#define DIM   1024
#define INNER 2048

// ---------------- device scratch ----------------
__device__ __align__(16) float g_qkvpart[8 * BATCH * 4096];    // [dc][b][j]
__device__ __align__(16) float g_colpart[16 * BATCH * INNER];  // [z][b][j]
__device__ __align__(16) float g_kp[BATCH * INNER];
__device__ __align__(16) float g_qp[BATCH * INNER];
__device__ __align__(16) float g_dv[BATCH * INNER];
__device__ __align__(16) float g_outv[BATCH * INNER];
__device__ __align__(16) float g_opart[64 * BATCH * DIM];      // [ic][b][jo]

// ---------------- K1: fused colsum(W) + qkv partial GEMM -------------
__global__ __launch_bounds__(256) void k_pass1(const float* __restrict__ x,
                                               const float* __restrict__ Wq,
                                               const float* __restrict__ Wk,
                                               const float* __restrict__ Wv,
                                               const float* __restrict__ W) {
    __shared__ __align__(16) float shx[32 * 128];
    const int bid = blockIdx.x, tid = threadIdx.x;

    if (bid < 1024) {
        // ---- colsum branch: block = (jc, b, z); 128 rows x 1024 cols ----
        const int jc = bid & 1, b = (bid >> 1) & 31, z = bid >> 6;
        const int c = jc * 1024 + tid * 4;
        const float4* p = (const float4*)(W + ((size_t)(b * INNER + z * 128)) * INNER + c);
        float4 a0 = {0,0,0,0}, a1 = {0,0,0,0}, a2 = {0,0,0,0}, a3 = {0,0,0,0};
        for (int r = 0; r < 128; r += 4) {
            float4 v0 = __ldcs(&p[(size_t)(r + 0) * 512]);
            float4 v1 = __ldcs(&p[(size_t)(r + 1) * 512]);
            float4 v2 = __ldcs(&p[(size_t)(r + 2) * 512]);
            float4 v3 = __ldcs(&p[(size_t)(r + 3) * 512]);
            a0.x += v0.x; a0.y += v0.y; a0.z += v0.z; a0.w += v0.w;
            a1.x += v1.x; a1.y += v1.y; a1.z += v1.z; a1.w += v1.w;
            a2.x += v2.x; a2.y += v2.y; a2.z += v2.z; a2.w += v2.w;
            a3.x += v3.x; a3.y += v3.y; a3.z += v3.z; a3.w += v3.w;
        }
        float4 s;
        s.x = (a0.x + a1.x) + (a2.x + a3.x);
        s.y = (a0.y + a1.y) + (a2.y + a3.y);
        s.z = (a0.z + a1.z) + (a2.z + a3.z);
        s.w = (a0.w + a1.w) + (a2.w + a3.w);
        *(float4*)(g_colpart + ((size_t)(z * 32 + b)) * INNER + c) = s;
    } else {
        // ---- qkv partial GEMM branch ----
        const int qid = bid - 1024;
        const int jc = qid & 15, dc = qid >> 4;
        for (int t = tid; t < 32 * 128; t += 256) {
            int b = t >> 7, dd = t & 127;
            shx[t] = x[b * DIM + dc * 128 + dd];
        }
        __syncthreads();

        const int j = jc * 256 + tid;  // 0..4095
        const float* Wm; int col, ncols;
        if (j < 1024)      { Wm = Wq; col = j;        ncols = 1024; }
        else if (j < 2048) { Wm = Wk; col = j - 1024; ncols = 1024; }
        else               { Wm = Wv; col = j - 2048; ncols = 2048; }

        float acc[32];
#pragma unroll
        for (int b = 0; b < 32; b++) acc[b] = 0.f;
        const float* wp = Wm + (size_t)(dc * 128) * ncols + col;
        for (int dd = 0; dd < 128; dd += 4) {
            float w0 = wp[(size_t)(dd + 0) * ncols];
            float w1 = wp[(size_t)(dd + 1) * ncols];
            float w2 = wp[(size_t)(dd + 2) * ncols];
            float w3 = wp[(size_t)(dd + 3) * ncols];
#pragma unroll
            for (int b = 0; b < 32; b++) {
                const float4 xv = *(const float4*)&shx[b * 128 + dd];
                acc[b] = fmaf(xv.x, w0, fmaf(xv.y, w1, fmaf(xv.z, w2, fmaf(xv.w, w3, acc[b]))));
            }
        }
#pragma unroll
        for (int b = 0; b < 32; b++)
            g_qkvpart[(size_t)(dc * 32 + b) * 4096 + j] = acc[b];
    }
}

// ---------------- K2: beta, kp, qp, dv (from L2-hot partials) --------
__device__ __forceinline__ float sum8_qkv(int b, int j) {
    float s = 0.f;
#pragma unroll
    for (int dc = 0; dc < 8; dc++) s += g_qkvpart[(size_t)(dc * 32 + b) * 4096 + j];
    return s;
}

__device__ __forceinline__ float feat(int b, int j, int base, const float* __restrict__ bias) {
    const int c = j & 1023;
    float v = sum8_qkv(b, base + c) + bias[c];
    v = (j < 1024) ? v : -v;
    return fmaxf(v, 0.f);
}

__global__ __launch_bounds__(256) void k_mid(const float* __restrict__ x,
                                             const float* __restrict__ Wb,
                                             const float* __restrict__ bb,
                                             const float* __restrict__ bq,
                                             const float* __restrict__ bk,
                                             const float* __restrict__ bv) {
    const int b = blockIdx.y, jc = blockIdx.x, tid = threadIdx.x;

    float s = 0.f;
    for (int d = tid; d < DIM; d += 256) s += x[b * DIM + d] * Wb[d];
#pragma unroll
    for (int o = 16; o; o >>= 1) s += __shfl_down_sync(0xffffffffu, s, o);
    __shared__ float shr[8];
    __shared__ float sbeta;
    if ((tid & 31) == 0) shr[tid >> 5] = s;
    __syncthreads();
    if (tid == 0) {
        float t = 0.f;
#pragma unroll
        for (int u = 0; u < 8; u++) t += shr[u];
        t += bb[0];
        sbeta = 1.f / (1.f + expf(-t));
    }
    __syncthreads();
    const float beta = sbeta;

    const int j = jc * 256 + tid;
    const int jm = (j + INNER - 1) & (INNER - 1);

    const float kpv = feat(b, j, 1024, bk) * feat(b, jm, 1024, bk);
    g_kp[b * INNER + j] = kpv;
    g_qp[b * INNER + j] = feat(b, j, 0, bq) * feat(b, jm, 0, bq);

    const float vv = sum8_qkv(b, 2048 + j) + bv[j];
    float cs = 0.f;
#pragma unroll
    for (int z = 0; z < 16; z++) cs += g_colpart[(size_t)(z * 32 + b) * INNER + j];
    g_dv[b * INNER + j] = beta * (vv - cs * kpv);
}

// ---------------- K3: W_new = W + dv⊗kp, fused row-sum --------------
// grid (256 rowgroups of 8, 32 b), 256 threads = 8 warps, one warp per row.
__global__ __launch_bounds__(256) void k_update(const float* __restrict__ W,
                                                float* __restrict__ wnew) {
    const int b = blockIdx.y, tid = threadIdx.x;
    const int i0 = blockIdx.x * 8;
    __shared__ __align__(16) float4 shkp[512];
    const float4* kpv4 = (const float4*)(g_kp + b * INNER);
    for (int t = tid; t < 512; t += 256) shkp[t] = kpv4[t];
    __syncthreads();

    const int w = tid >> 5, lane = tid & 31;
    const int i = i0 + w;
    const size_t base = ((size_t)b * INNER + i) * INNER;
    const float4* Wr = (const float4*)(W + base);
    float4* Or = (float4*)(wnew + base);
    const float dvi = g_dv[b * INNER + i];

    float lsum = 0.f;
#pragma unroll
    for (int t = lane; t < 512; t += 32) {
        float4 wv = __ldcs(&Wr[t]);
        float4 kp4 = shkp[t];
        float4 r;
        r.x = fmaf(dvi, kp4.x, wv.x);
        r.y = fmaf(dvi, kp4.y, wv.y);
        r.z = fmaf(dvi, kp4.z, wv.z);
        r.w = fmaf(dvi, kp4.w, wv.w);
        __stcs(&Or[t], r);
        lsum += (r.x + r.y) + (r.z + r.w);
    }
#pragma unroll
    for (int o = 16; o; o >>= 1) lsum += __shfl_down_sync(0xffffffffu, lsum, o);
    if (lane == 0) g_outv[b * INNER + i] = lsum * g_qp[b * INNER + i];
}

// ---------------- K4: out partials = outv @ Wo -----------------------
// grid (4 jc, 64 ic, 4 bg): acc[8] scalar -> regs ~40, occupancy ~63%.
__global__ __launch_bounds__(256) void k_outpart(const float* __restrict__ Wo) {
    __shared__ __align__(16) float sh[8 * 32];
    const int jc = blockIdx.x, ic = blockIdx.y, bg = blockIdx.z, tid = threadIdx.x;
    if (tid < 8 * 32) {
        int bb = tid >> 5, ii = tid & 31;
        sh[tid] = g_outv[(bg * 8 + bb) * INNER + ic * 32 + ii];
    }
    __syncthreads();

    const int jo = jc * 256 + tid;
    float acc[8];
#pragma unroll
    for (int bb = 0; bb < 8; bb++) acc[bb] = 0.f;
    const float* wp = Wo + (size_t)(ic * 32) * DIM + jo;
#pragma unroll
    for (int ii = 0; ii < 32; ii += 4) {
        float w0 = wp[(size_t)(ii + 0) * DIM];
        float w1 = wp[(size_t)(ii + 1) * DIM];
        float w2 = wp[(size_t)(ii + 2) * DIM];
        float w3 = wp[(size_t)(ii + 3) * DIM];
#pragma unroll
        for (int bb = 0; bb < 8; bb++) {
            const float4 xv = *(const float4*)&sh[bb * 32 + ii];
            acc[bb] = fmaf(xv.x, w0, fmaf(xv.y, w1, fmaf(xv.z, w2, fmaf(xv.w, w3, acc[bb]))));
        }
    }
#pragma unroll
    for (int bb = 0; bb < 8; bb++)
        g_opart[(size_t)(ic * 32 + bg * 8 + bb) * DIM + jo] = acc[bb];
}

// ---------------- K5: out finalize -----------------------------------
__global__ __launch_bounds__(256) void k_outfinal(const float* __restrict__ bo,
                                                  float* __restrict__ out) {
    const int idx = blockIdx.x * 256 + threadIdx.x;  // 32768
    const int jo = idx & 1023, b = idx >> 10;
    float s = bo[jo];
#pragma unroll
    for (int ic = 0; ic < 64; ic++) s += g_opart[(size_t)(ic * 32 + b) * DIM + jo];
    out[idx] = s;
}

// ---------------- launch ---------------------------------------------
extern "C" void kernel_launch(void* const* d_in, const int* in_sizes, int n_in,
                              void* d_out, int out_size) {
    const float* x  = (const float*)d_in[0];
    const float* W  = (const float*)d_in[1];
    const float* Wq = (const float*)d_in[2];
    const float* bq = (const float*)d_in[3];
    const float* Wk = (const float*)d_in[4];
    const float* bk = (const float*)d_in[5];
    const float* Wv = (const float*)d_in[6];
    const float* bv = (const float*)d_in[7];
    const float* Wo = (const float*)d_in[8];
    const float* bo = (const float*)d_in[9];
    const float* Wb = (const float*)d_in[10];
    const float* bb = (const float*)d_in[11];

    float* out  = (float*)d_out;
    float* wnew = out + BATCH * DIM;

    k_pass1   <<<1152,           256>>>(x, Wq, Wk, Wv, W);
    k_mid     <<<dim3(8, 32),    256>>>(x, Wb, bb, bq, bk, bv);
    k_update  <<<dim3(256, 32),  256>>>(W, wnew);
    k_outpart <<<dim3(4, 64, 4), 256>>>(Wo);
    k_outfinal<<<128,            256>>>(bo, out);
}